// round 11
// baseline (speedup 1.0000x reference)
#include <cuda_runtime.h>
#include <cstdint>

// ---------------------------------------------------------------------------
// CTC loss (forward, sum over batch, zero_infinity) on GB300 — two-phase,
// single-warp LOG2-domain scan; cp.async ring with CHUNKED commit groups.
//
// Phase 1 (ctc_emit_kernel): em[t][b][l] = logp[t][b][ext_b[l]] * log2(e),
//   packed 8 floats per (t,b,lane): g_em[((t*B+b)*32 + lane)*8 + r],
//   column l = lane*7 + r (r in 0..6; slot 7 is padding).
//
// Phase 2 (ctc_alpha_kernel): ONE WARP per batch element, lane i owns columns
//   [i*7, i*7+7). log2-alphas in registers; halo via 2 shfl_up; lse3 with
//   exact median-of-3 (ex2 args <= 0: overflow/NaN free).
//
//   KEY FIX this round: ring = 4 chunks x 8 rows; ONE cp.async.commit_group
//   and ONE wait_group<2> per 8 steps (R10 did both every step -> the DEPBAR
//   was on the serial path every step). wait_group<2> leaves the 2 newest
//   chunk-groups in flight, so the chunk being consumed AND the next one are
//   complete: >= 16 rows (~2800 cyc) of prefetch cover, 1/8th the wait cost.
// ---------------------------------------------------------------------------

#define NEGF (-1.0e30f)
#define LOG2E 1.4426950408889634f
#define LN2   0.6931471805599453f
#define R     7
#define CH    8                          // rows per chunk
#define NCH   4                          // chunks in ring (32 rows total)
#define RROWS (CH * NCH)                 // 32
#define EM_ROWS (1000 + 40)
#define EM_CAP (EM_ROWS * 32 * 32 * 8)

__device__ __align__(128) float g_em[EM_CAP];
__device__ float g_loss[8192];
__device__ unsigned g_done;

__device__ __forceinline__ float ex2f(float x) {
    float r; asm("ex2.approx.f32 %0, %1;" : "=f"(r) : "f"(x)); return r;
}
__device__ __forceinline__ float lg2f(float x) {
    float r; asm("lg2.approx.f32 %0, %1;" : "=f"(r) : "f"(x)); return r;
}
__device__ __forceinline__ void cp16(uint32_t dst, const float* src) {
    asm volatile("cp.async.cg.shared.global [%0], [%1], 16;"
                 :: "r"(dst), "l"(src) : "memory");
}
__device__ __forceinline__ void cp_commit() {
    asm volatile("cp.async.commit_group;" ::: "memory");
}
template <int N>
__device__ __forceinline__ void cp_wait() {
    asm volatile("cp.async.wait_group %0;" :: "n"(N) : "memory");
}

// lse3 in log2 domain; exact median-of-3 -> ex2 args provably <= 0.
__device__ __forceinline__ float lse3_2(float a0, float a1, float a2) {
    const float mx01 = fmaxf(a0, a1);
    const float mn01 = fminf(a0, a1);
    const float mx   = fmaxf(mx01, a2);
    const float md   = fmaxf(mn01, fminf(mx01, a2));
    const float mn   = fminf(mn01, a2);
    const float s    = 1.0f + ex2f(md - mx) + ex2f(mn - mx);
    return mx + lg2f(s);
}

// ---- Phase 1: emit gather (log2 units), one CTA per (t, b) pair ------------
__global__ void ctc_emit_kernel(const float* __restrict__ logp,
                                const int*   __restrict__ targets,
                                const int*   __restrict__ target_lens,
                                int B, int C, int S, int L)
{
    const int z = blockIdx.x;          // z = t*B + b
    const int b = z % B;
    const int l = threadIdx.x;         // 0 .. 223

    const int Lb = 2 * target_lens[b] + 1;

    float p = 0.0f;
    if (l < L && l < Lb) {
        int e = 0;
        if (l & 1) e = targets[b * S + (l >> 1)];
        p = __ldcs(&logp[(size_t)z * C + e]) * LOG2E;
    }
    const int lane = l / R;
    const int r    = l % R;
    g_em[(((size_t)z * 32) + lane) * 8 + r] = p;
}

// ---- Phase 2: single-warp log-domain alpha scan + fused reduction ----------
__global__ void __launch_bounds__(32, 1)
ctc_alpha_kernel(const int* __restrict__ targets,
                 const int* __restrict__ input_lens,
                 const int* __restrict__ target_lens,
                 float* __restrict__ out,
                 int B, int S)
{
    __shared__ __align__(16) float ring[RROWS][32][8];   // 32 KB
    // Global row r lives at ring row (r-1) & 31 (rows 1..32 fill 0..31;
    // refills preserve the mapping: tb = 8k+1 => (tb+32-1)&31 = (k&3)*8).

    const int b    = blockIdx.x;
    const int lane = threadIdx.x;
    const unsigned FULL = 0xffffffffu;

    const int tl = target_lens[b];
    const int il = input_lens[b];
    const int Lb = 2 * tl + 1;

    // Skip-transition flags for this lane's columns.
    bool sk[R];
#pragma unroll
    for (int r = 0; r < R; ++r) {
        const int l = lane * R + r;
        bool s = false;
        if ((l & 1) && l >= 3 && l < Lb) {
            const int c  = targets[b * S + (l >> 1)];
            const int pc = targets[b * S + (l >> 1) - 1];
            s = (c != pc);
        }
        sk[r] = s;
    }

    const size_t strideT = (size_t)B * 256;                 // floats per timestep
    const float* base = g_em + ((size_t)b * 32 + lane) * 8; // + t*strideT

    const uint32_t smem0 =
        (uint32_t)__cvta_generic_to_shared(&ring[0][0][0]) + (uint32_t)lane * 32u;

    // t = 0 init: log-alpha = em at columns 0,1 (lane 0), else -1e30.
    float la[R];
#pragma unroll
    for (int r = 0; r < R; ++r) la[r] = NEGF;
    if (lane == 0) { la[0] = base[0]; la[1] = base[1]; }

    // ---- Prologue: rows 1..32 into the ring, one commit group per chunk ----
#pragma unroll
    for (int c = 0; c < NCH; ++c) {
#pragma unroll
        for (int j = 0; j < CH; ++j) {
            const int rr = c * CH + j;                 // ring row = global row-1
            const float* src = base + (size_t)(1 + rr) * strideT;
            const uint32_t dst = smem0 + (uint32_t)rr * 1024u;
            cp16(dst, src);
            cp16(dst + 16u, src + 4);
        }
        cp_commit();
    }
    cp_wait<2>();                          // chunks 0,1 resident
    float4 r0 = *(const float4*)&ring[0][lane][0];   // row 1
    float4 r1 = *(const float4*)&ring[0][lane][4];

    // ---- Main loop: one wait + one commit per 8 steps -----------------------
    int tb = 1;
    int k  = 0;
    for (; tb + CH <= il; tb += CH, ++k) {
        cp_wait<2>();   // all but 2 newest groups done -> slots k&3, (k+1)&3 resident
        const int pos = (8 * k) & 31;      // ring row of global row tb

#pragma unroll
        for (int j = 0; j < CH; ++j) {
            // Stage row t+1 = tb+j+1 at ring row (pos + 1 + j) & 31.
            const int rr = (pos + 1 + j) & 31;
            const float4 n0 = *(const float4*)&ring[rr][lane][0];
            const float4 n1 = *(const float4*)&ring[rr][lane][4];

            // Halo: left lane's two rightmost OLD log-alphas.
            float L1 = __shfl_up_sync(FULL, la[R - 1], 1);
            float L2 = __shfl_up_sync(FULL, la[R - 2], 1);
            if (lane == 0) { L1 = NEGF; L2 = NEGF; }

            // In-place descending update with row t (r0, r1).
            la[6] = lse3_2(la[6], la[5], sk[6] ? la[4] : NEGF) + r1.z;
            la[5] = lse3_2(la[5], la[4], sk[5] ? la[3] : NEGF) + r1.y;
            la[4] = lse3_2(la[4], la[3], sk[4] ? la[2] : NEGF) + r1.x;
            la[3] = lse3_2(la[3], la[2], sk[3] ? la[1] : NEGF) + r0.w;
            la[2] = lse3_2(la[2], la[1], sk[2] ? la[0] : NEGF) + r0.z;
            la[1] = lse3_2(la[1], la[0], sk[1] ? L1    : NEGF) + r0.y;
            la[0] = lse3_2(la[0], L1,    sk[0] ? L2    : NEGF) + r0.x;

            r0 = n0; r1 = n1;
        }

        // Refill the just-consumed chunk (slot k&3) with rows tb+32..tb+39.
        {
            const float*  src = base + (size_t)(tb + 32) * strideT;
            const uint32_t dst0 = smem0 + (uint32_t)pos * 1024u;
#pragma unroll
            for (int j = 0; j < CH; ++j) {
                const float* s = src + (size_t)j * strideT;
                const uint32_t d = dst0 + (uint32_t)j * 1024u;
                cp16(d, s);
                cp16(d + 16u, s + 4);
            }
            cp_commit();
        }
    }
    cp_wait<0>();   // drain before tail / exit

    // ---- Tail: remaining < 8 steps, direct global loads ---------------------
    for (int t = tb; t < il; ++t) {
        const float* p = base + (size_t)t * strideT;
        const float4 q0 = *(const float4*)(p);
        const float4 q1 = *(const float4*)(p + 4);

        float L1 = __shfl_up_sync(FULL, la[R - 1], 1);
        float L2 = __shfl_up_sync(FULL, la[R - 2], 1);
        if (lane == 0) { L1 = NEGF; L2 = NEGF; }

        la[6] = lse3_2(la[6], la[5], sk[6] ? la[4] : NEGF) + q1.z;
        la[5] = lse3_2(la[5], la[4], sk[5] ? la[3] : NEGF) + q1.y;
        la[4] = lse3_2(la[4], la[3], sk[4] ? la[2] : NEGF) + q1.x;
        la[3] = lse3_2(la[3], la[2], sk[3] ? la[1] : NEGF) + q0.w;
        la[2] = lse3_2(la[2], la[1], sk[2] ? la[0] : NEGF) + q0.z;
        la[1] = lse3_2(la[1], la[0], sk[1] ? L1    : NEGF) + q0.y;
        la[0] = lse3_2(la[0], L1,    sk[0] ? L2    : NEGF) + q0.x;
    }

    // Final cells: columns 2*tl (blank) and 2*tl-1 (last label), log2 units.
    const int c1 = 2 * tl;
    const int c2 = (tl >= 1) ? (2 * tl - 1) : 0;
    const int r1i = c1 % R, i1 = c1 / R;
    const int r2i = c2 % R, i2 = c2 / R;

    float x1 = la[0], x2 = la[0];
#pragma unroll
    for (int r = 1; r < R; ++r) {
        if (r == r1i) x1 = la[r];
        if (r == r2i) x2 = la[r];
    }
    x1 = __shfl_sync(FULL, x1, i1);
    x2 = __shfl_sync(FULL, x2, i2);

    int last = 0;
    if (lane == 0) {
        if (tl < 1) x2 = NEGF;
        const float m = fmaxf(x1, x2);
        float loss = -LN2 * (m + lg2f(ex2f(x1 - m) + ex2f(x2 - m)));
        if (!(loss < 5.0e29f)) loss = 0.0f;        // zero_infinity
        g_loss[b] = loss;
        __threadfence();
        const unsigned n = atomicAdd(&g_done, 1u);
        last = (n == (unsigned)(gridDim.x - 1));
    }

    last = __shfl_sync(FULL, last, 0);
    if (last) {
        float s = 0.0f;
        for (int i = lane; i < B; i += 32) s += g_loss[i];
#pragma unroll
        for (int o = 16; o; o >>= 1) s += __shfl_xor_sync(FULL, s, o);
        if (lane == 0) {
            out[0] = s;
            g_done = 0u;
        }
    }
}

extern "C" void kernel_launch(void* const* d_in, const int* in_sizes, int n_in,
                              void* d_out, int out_size)
{
    const float* logp        = (const float*)d_in[0];
    const int*   targets     = (const int*)  d_in[1];
    const int*   input_lens  = (const int*)  d_in[2];
    const int*   target_lens = (const int*)  d_in[3];

    const int B = in_sizes[2];
    const int S = in_sizes[1] / B;
    const int C = 1000;
    const int T = (int)((long long)in_sizes[0] / ((long long)B * (long long)C));

    const int L = 2 * S + 1;              // requires L <= 224 (S <= 111)

    ctc_emit_kernel<<<T * B, 224>>>(logp, targets, target_lens, B, C, S, L);
    ctc_alpha_kernel<<<B, 32>>>(targets, input_lens, target_lens,
                                (float*)d_out, B, S);
}

// round 12
// speedup vs baseline: 1.0258x; 1.0258x over previous
#include <cuda_runtime.h>
#include <cstdint>

// ---------------------------------------------------------------------------
// CTC loss (forward, sum over batch, zero_infinity) on GB300 — two-phase,
// single-warp LOG2-domain scan; cp.async chunked ring; STAGE-MAJOR inner loop.
//
// Phase 1 (ctc_emit_kernel): em[t][b][l] = logp[t][b][ext_b[l]] * log2(e),
//   packed 8 floats per (t,b,lane): g_em[((t*B+b)*32 + lane)*8 + r],
//   column l = lane*7 + r (r in 0..6; slot 7 is padding).
//
// Phase 2 (ctc_alpha_kernel): ONE WARP per batch element, lane i owns columns
//   [i*7, i*7+7). log2-alphas in registers; halo via 2 shfl_up; lse3 with
//   exact median-of-3 (ex2 args <= 0: overflow/NaN free).
//
//   KEY FIX this round: the 7 per-column lse3 chains are emitted STAGE-MAJOR
//   (all minmax, then all 14 ex2 back-to-back, then sums, then all 7 lg2),
//   exposing their independence to the scheduler. The column-major form was
//   executing the chains serially (~7 x 64 cyc = measured ~550 cyc/step);
//   interleaved, the floor is MUFU issue: 21 x 8 = 168 cyc/step.
// ---------------------------------------------------------------------------

#define NEGF (-1.0e30f)
#define LOG2E 1.4426950408889634f
#define LN2   0.6931471805599453f
#define R     7
#define CH    8                          // rows per chunk
#define NCH   4                          // chunks in ring (32 rows total)
#define RROWS (CH * NCH)                 // 32
#define EM_ROWS (1000 + 40)
#define EM_CAP (EM_ROWS * 32 * 32 * 8)

__device__ __align__(128) float g_em[EM_CAP];
__device__ float g_loss[8192];
__device__ unsigned g_done;

__device__ __forceinline__ float ex2f(float x) {
    float r; asm("ex2.approx.f32 %0, %1;" : "=f"(r) : "f"(x)); return r;
}
__device__ __forceinline__ float lg2f(float x) {
    float r; asm("lg2.approx.f32 %0, %1;" : "=f"(r) : "f"(x)); return r;
}
__device__ __forceinline__ void cp16(uint32_t dst, const float* src) {
    asm volatile("cp.async.cg.shared.global [%0], [%1], 16;"
                 :: "r"(dst), "l"(src) : "memory");
}
__device__ __forceinline__ void cp_commit() {
    asm volatile("cp.async.commit_group;" ::: "memory");
}
template <int N>
__device__ __forceinline__ void cp_wait() {
    asm volatile("cp.async.wait_group %0;" :: "n"(N) : "memory");
}

// ---- Phase 1: emit gather (log2 units), one CTA per (t, b) pair ------------
__global__ void ctc_emit_kernel(const float* __restrict__ logp,
                                const int*   __restrict__ targets,
                                const int*   __restrict__ target_lens,
                                int B, int C, int S, int L)
{
    const int z = blockIdx.x;          // z = t*B + b
    const int b = z % B;
    const int l = threadIdx.x;         // 0 .. 223

    const int Lb = 2 * target_lens[b] + 1;

    float p = 0.0f;
    if (l < L && l < Lb) {
        int e = 0;
        if (l & 1) e = targets[b * S + (l >> 1)];
        p = __ldcs(&logp[(size_t)z * C + e]) * LOG2E;
    }
    const int lane = l / R;
    const int r    = l % R;
    g_em[(((size_t)z * 32) + lane) * 8 + r] = p;
}

// Stage-major lse3 update for all 7 columns. la is updated in place.
// A1[r] = old la[r-1] (halo L1 for r=0); A2[r] = skip-gated old la[r-2].
__device__ __forceinline__ void step7(float la[R], float L1, float L2,
                                      const bool sk[R],
                                      float e0, float e1, float e2c, float e3,
                                      float e4, float e5, float e6)
{
    float A1[R], A2[R];
    A1[0] = L1;
#pragma unroll
    for (int r = 1; r < R; ++r) A1[r] = la[r - 1];
    A2[0] = sk[0] ? L2 : NEGF;
    A2[1] = sk[1] ? L1 : NEGF;
#pragma unroll
    for (int r = 2; r < R; ++r) A2[r] = sk[r] ? la[r - 2] : NEGF;

    float mx01[R], mn01[R];
#pragma unroll
    for (int r = 0; r < R; ++r) { mx01[r] = fmaxf(la[r], A1[r]);
                                  mn01[r] = fminf(la[r], A1[r]); }
    float mx[R], md[R], mn[R];
#pragma unroll
    for (int r = 0; r < R; ++r) mx[r] = fmaxf(mx01[r], A2[r]);
#pragma unroll
    for (int r = 0; r < R; ++r) md[r] = fmaxf(mn01[r], fminf(mx01[r], A2[r]));
#pragma unroll
    for (int r = 0; r < R; ++r) mn[r] = fminf(mn01[r], A2[r]);

    float d1[R], d2[R];
#pragma unroll
    for (int r = 0; r < R; ++r) d1[r] = md[r] - mx[r];
#pragma unroll
    for (int r = 0; r < R; ++r) d2[r] = mn[r] - mx[r];

    float E1[R], E2[R];
#pragma unroll
    for (int r = 0; r < R; ++r) E1[r] = ex2f(d1[r]);   // 14 MUFU back-to-back
#pragma unroll
    for (int r = 0; r < R; ++r) E2[r] = ex2f(d2[r]);

    float s[R];
#pragma unroll
    for (int r = 0; r < R; ++r) s[r] = 1.0f + E1[r] + E2[r];

    float lg[R];
#pragma unroll
    for (int r = 0; r < R; ++r) lg[r] = lg2f(s[r]);    // 7 MUFU back-to-back

    la[0] = mx[0] + lg[0] + e0;
    la[1] = mx[1] + lg[1] + e1;
    la[2] = mx[2] + lg[2] + e2c;
    la[3] = mx[3] + lg[3] + e3;
    la[4] = mx[4] + lg[4] + e4;
    la[5] = mx[5] + lg[5] + e5;
    la[6] = mx[6] + lg[6] + e6;
}

// ---- Phase 2: single-warp log-domain alpha scan + fused reduction ----------
__global__ void __launch_bounds__(32, 1)
ctc_alpha_kernel(const int* __restrict__ targets,
                 const int* __restrict__ input_lens,
                 const int* __restrict__ target_lens,
                 float* __restrict__ out,
                 int B, int S)
{
    __shared__ __align__(16) float ring[RROWS][32][8];   // 32 KB
    // Global row r lives at ring row (r-1) & 31.

    const int b    = blockIdx.x;
    const int lane = threadIdx.x;
    const unsigned FULL = 0xffffffffu;

    const int tl = target_lens[b];
    const int il = input_lens[b];
    const int Lb = 2 * tl + 1;

    // Skip-transition flags for this lane's columns.
    bool sk[R];
#pragma unroll
    for (int r = 0; r < R; ++r) {
        const int l = lane * R + r;
        bool s = false;
        if ((l & 1) && l >= 3 && l < Lb) {
            const int c  = targets[b * S + (l >> 1)];
            const int pc = targets[b * S + (l >> 1) - 1];
            s = (c != pc);
        }
        sk[r] = s;
    }

    const size_t strideT = (size_t)B * 256;                 // floats per timestep
    const float* base = g_em + ((size_t)b * 32 + lane) * 8; // + t*strideT

    const uint32_t smem0 =
        (uint32_t)__cvta_generic_to_shared(&ring[0][0][0]) + (uint32_t)lane * 32u;

    // t = 0 init: log-alpha = em at columns 0,1 (lane 0), else -1e30.
    float la[R];
#pragma unroll
    for (int r = 0; r < R; ++r) la[r] = NEGF;
    if (lane == 0) { la[0] = base[0]; la[1] = base[1]; }

    // ---- Prologue: rows 1..32 into the ring, one commit group per chunk ----
#pragma unroll
    for (int c = 0; c < NCH; ++c) {
#pragma unroll
        for (int j = 0; j < CH; ++j) {
            const int rr = c * CH + j;                 // ring row = global row-1
            const float* src = base + (size_t)(1 + rr) * strideT;
            const uint32_t dst = smem0 + (uint32_t)rr * 1024u;
            cp16(dst, src);
            cp16(dst + 16u, src + 4);
        }
        cp_commit();
    }
    cp_wait<2>();                          // chunks 0,1 resident
    float4 r0 = *(const float4*)&ring[0][lane][0];   // row 1
    float4 r1 = *(const float4*)&ring[0][lane][4];

    // ---- Main loop: one wait + one commit per 8 steps -----------------------
    int tb = 1;
    int k  = 0;
    for (; tb + CH <= il; tb += CH, ++k) {
        cp_wait<2>();   // slots k&3 and (k+1)&3 resident
        const int pos = (8 * k) & 31;      // ring row of global row tb

#pragma unroll
        for (int j = 0; j < CH; ++j) {
            // Stage row t+1 at ring row (pos + 1 + j) & 31.
            const int rr = (pos + 1 + j) & 31;
            const float4 n0 = *(const float4*)&ring[rr][lane][0];
            const float4 n1 = *(const float4*)&ring[rr][lane][4];

            // Halo: left lane's two rightmost OLD log-alphas.
            float L1 = __shfl_up_sync(FULL, la[R - 1], 1);
            float L2 = __shfl_up_sync(FULL, la[R - 2], 1);
            if (lane == 0) { L1 = NEGF; L2 = NEGF; }

            step7(la, L1, L2, sk, r0.x, r0.y, r0.z, r0.w, r1.x, r1.y, r1.z);

            r0 = n0; r1 = n1;
        }

        // Refill the just-consumed chunk (slot k&3) with rows tb+32..tb+39.
        {
            const float*  src = base + (size_t)(tb + 32) * strideT;
            const uint32_t dst0 = smem0 + (uint32_t)pos * 1024u;
#pragma unroll
            for (int j = 0; j < CH; ++j) {
                const float* s = src + (size_t)j * strideT;
                const uint32_t d = dst0 + (uint32_t)j * 1024u;
                cp16(d, s);
                cp16(d + 16u, s + 4);
            }
            cp_commit();
        }
    }
    cp_wait<0>();   // drain before tail / exit

    // ---- Tail: remaining < 8 steps, direct global loads ---------------------
    for (int t = tb; t < il; ++t) {
        const float* p = base + (size_t)t * strideT;
        const float4 q0 = *(const float4*)(p);
        const float4 q1 = *(const float4*)(p + 4);

        float L1 = __shfl_up_sync(FULL, la[R - 1], 1);
        float L2 = __shfl_up_sync(FULL, la[R - 2], 1);
        if (lane == 0) { L1 = NEGF; L2 = NEGF; }

        step7(la, L1, L2, sk, q0.x, q0.y, q0.z, q0.w, q1.x, q1.y, q1.z);
    }

    // Final cells: columns 2*tl (blank) and 2*tl-1 (last label), log2 units.
    const int c1 = 2 * tl;
    const int c2 = (tl >= 1) ? (2 * tl - 1) : 0;
    const int r1i = c1 % R, i1 = c1 / R;
    const int r2i = c2 % R, i2 = c2 / R;

    float x1 = la[0], x2 = la[0];
#pragma unroll
    for (int r = 1; r < R; ++r) {
        if (r == r1i) x1 = la[r];
        if (r == r2i) x2 = la[r];
    }
    x1 = __shfl_sync(FULL, x1, i1);
    x2 = __shfl_sync(FULL, x2, i2);

    int last = 0;
    if (lane == 0) {
        if (tl < 1) x2 = NEGF;
        const float m = fmaxf(x1, x2);
        float loss = -LN2 * (m + lg2f(ex2f(x1 - m) + ex2f(x2 - m)));
        if (!(loss < 5.0e29f)) loss = 0.0f;        // zero_infinity
        g_loss[b] = loss;
        __threadfence();
        const unsigned n = atomicAdd(&g_done, 1u);
        last = (n == (unsigned)(gridDim.x - 1));
    }

    last = __shfl_sync(FULL, last, 0);
    if (last) {
        float s = 0.0f;
        for (int i = lane; i < B; i += 32) s += g_loss[i];
#pragma unroll
        for (int o = 16; o; o >>= 1) s += __shfl_xor_sync(FULL, s, o);
        if (lane == 0) {
            out[0] = s;
            g_done = 0u;
        }
    }
}

extern "C" void kernel_launch(void* const* d_in, const int* in_sizes, int n_in,
                              void* d_out, int out_size)
{
    const float* logp        = (const float*)d_in[0];
    const int*   targets     = (const int*)  d_in[1];
    const int*   input_lens  = (const int*)  d_in[2];
    const int*   target_lens = (const int*)  d_in[3];

    const int B = in_sizes[2];
    const int S = in_sizes[1] / B;
    const int C = 1000;
    const int T = (int)((long long)in_sizes[0] / ((long long)B * (long long)C));

    const int L = 2 * S + 1;              // requires L <= 224 (S <= 111)

    ctc_emit_kernel<<<T * B, 224>>>(logp, targets, target_lens, B, C, S, L);
    ctc_alpha_kernel<<<B, 32>>>(targets, input_lens, target_lens,
                                (float*)d_out, B, S);
}

// round 13
// speedup vs baseline: 2.6901x; 2.6225x over previous
#include <cuda_runtime.h>
#include <cstdint>

// ---------------------------------------------------------------------------
// CTC loss (forward, sum over batch, zero_infinity) on GB300 — two-phase.
//
// Phase 1 (ctc_emit_kernel): em[t][b][l] = logp[t][b][ext_b[l]] * log2(e),
//   packed 2 floats per (t,b,thread): g_em[((t*B+b)*128 + tid)*2 + c],
//   column l = 2*tid + c.
//
// Phase 2 (ctc_alpha_kernel): ONE CTA of 128 threads (4 warps) per batch
//   element; thread tid owns columns 2*tid (blank: lse2, never skips) and
//   2*tid+1 (label: lse3). Per-thread/step: 5 MUFU, 1 shfl. Cross-warp halo
//   (left thread's odd-column alpha) via parity-double-buffered smem with a
//   single __syncthreads per step. Emit rows via cp.async chunked ring
//   (1 commit + 1 wait_group<2> per 8 steps). Log2-domain lse with exact
//   median-of-3 (ex2 args <= 0: overflow/NaN free). Fused final reduction.
// ---------------------------------------------------------------------------

#define NEGF (-1.0e30f)
#define LOG2E 1.4426950408889634f
#define LN2   0.6931471805599453f
#define TPB   128
#define NW    4
#define CH    8                          // rows per chunk
#define NCH   4                          // chunks in ring
#define RROWS 32
#define EM_ROWS (1000 + 40)
#define EM_CAP (EM_ROWS * 32 * 256)      // (T+40) * B * 256 floats (~34MB)

__device__ __align__(128) float g_em[EM_CAP];
__device__ float g_loss[8192];
__device__ unsigned g_done;

__device__ __forceinline__ float ex2f(float x) {
    float r; asm("ex2.approx.f32 %0, %1;" : "=f"(r) : "f"(x)); return r;
}
__device__ __forceinline__ float lg2f(float x) {
    float r; asm("lg2.approx.f32 %0, %1;" : "=f"(r) : "f"(x)); return r;
}
__device__ __forceinline__ void cp8(uint32_t dst, const float* src) {
    asm volatile("cp.async.ca.shared.global [%0], [%1], 8;"
                 :: "r"(dst), "l"(src) : "memory");
}
__device__ __forceinline__ void cp_commit() {
    asm volatile("cp.async.commit_group;" ::: "memory");
}
template <int N>
__device__ __forceinline__ void cp_wait() {
    asm volatile("cp.async.wait_group %0;" :: "n"(N) : "memory");
}

// log2-domain lse3, exact median-of-3 (both ex2 args <= 0).
__device__ __forceinline__ float lse3_2(float a0, float a1, float a2) {
    const float mx01 = fmaxf(a0, a1);
    const float mn01 = fminf(a0, a1);
    const float mx   = fmaxf(mx01, a2);
    const float md   = fmaxf(mn01, fminf(mx01, a2));
    const float mn   = fminf(mn01, a2);
    return mx + lg2f(1.0f + ex2f(md - mx) + ex2f(mn - mx));
}
// log2-domain lse2.
__device__ __forceinline__ float lse2_2(float a0, float a1) {
    const float mx = fmaxf(a0, a1);
    const float mn = fminf(a0, a1);
    return mx + lg2f(1.0f + ex2f(mn - mx));
}

// ---- Phase 1: emit gather (log2 units), one CTA per (t, b) pair ------------
__global__ void ctc_emit_kernel(const float* __restrict__ logp,
                                const int*   __restrict__ targets,
                                const int*   __restrict__ target_lens,
                                int B, int C, int S, int L)
{
    const int z = blockIdx.x;          // z = t*B + b
    const int b = z % B;
    const int l = threadIdx.x;         // 0 .. 255

    const int Lb = 2 * target_lens[b] + 1;

    float p = 0.0f;
    if (l < L && l < Lb) {
        int e = 0;
        if (l & 1) e = targets[b * S + (l >> 1)];
        p = __ldcs(&logp[(size_t)z * C + e]) * LOG2E;
    }
    g_em[((size_t)z * 128 + (l >> 1)) * 2 + (l & 1)] = p;
}

// ---- Phase 2: 4-warp log-domain alpha scan + fused reduction ---------------
__global__ void __launch_bounds__(TPB, 1)
ctc_alpha_kernel(const int* __restrict__ targets,
                 const int* __restrict__ input_lens,
                 const int* __restrict__ target_lens,
                 float* __restrict__ out,
                 int B, int S)
{
    __shared__ __align__(16) float ring[RROWS][TPB][2];   // 32 KB
    __shared__ float halo_s[2][NW];     // [parity][warp] = that warp's la1 of lane31
    __shared__ float fin[2];
    __shared__ int   s_last;

    const int b    = blockIdx.x;
    const int tid  = threadIdx.x;
    const int lane = tid & 31;
    const int w    = tid >> 5;
    const unsigned FULL = 0xffffffffu;

    const int tl = target_lens[b];
    const int il = input_lens[b];
    const int Lb = 2 * tl + 1;

    // Skip flag for the odd (label) column l1 = 2*tid+1; even column never skips.
    bool sk1 = false;
    {
        const int l1 = 2 * tid + 1;
        if (l1 >= 3 && l1 < Lb) {
            const int c  = targets[b * S + tid];
            const int pc = targets[b * S + tid - 1];
            sk1 = (c != pc);
        }
    }

    const size_t strideT = (size_t)B * 256;                    // floats per timestep
    const float* base = g_em + ((size_t)b * 128 + tid) * 2;    // + t*strideT

    const uint32_t smem0 =
        (uint32_t)__cvta_generic_to_shared(&ring[0][0][0]) + (uint32_t)tid * 8u;

    // t = 0 init: columns 0,1 (thread 0) get em[0]; all else -1e30.
    float la0 = NEGF, la1 = NEGF;
    if (tid == 0) { la0 = base[0]; la1 = base[1]; }

    // Initial halo (old la1 of each warp's lane31 = NEGF), parity 0 (read at t=1).
    if (lane == 31) halo_s[0][w] = la1;
    if (tid == 0) { fin[1] = NEGF; s_last = 0; }

    // ---- Prologue: rows 1..32 into the ring, one commit group per chunk ----
#pragma unroll
    for (int c = 0; c < NCH; ++c) {
#pragma unroll
        for (int j = 0; j < CH; ++j) {
            const int rr = c * CH + j;                 // ring row = global row-1
            cp8(smem0 + (uint32_t)rr * (TPB * 8u), base + (size_t)(1 + rr) * strideT);
        }
        cp_commit();
    }
    cp_wait<2>();
    __syncthreads();                       // halo_s[0] + ring row 1 visible
    float2 er = *(const float2*)&ring[0][tid][0];   // row 1 staged

    // ---- Main loop: one wait + one commit per 8 steps; 1 bar per step -------
    int tb = 1;
    int k  = 0;
    for (; tb + CH <= il; tb += CH, ++k) {
        cp_wait<2>();                      // chunks k&3 and (k+1)&3 resident
        const int pos = (8 * k) & 31;      // ring row of global row tb

#pragma unroll
        for (int j = 0; j < CH; ++j) {
            // parities are compile-time: tb is odd, so (t-1)&1 == j&1.
            const int pr = j & 1;          // read parity
            const int pw = (j + 1) & 1;    // write parity

            // Stage next row (t+1) from the ring.
            const int rr = (pos + 1 + j) & 31;
            const float2 nx = *(const float2*)&ring[rr][tid][0];

            // Halo: old la1 of the column to the left (l = 2*tid - 1).
            float P1 = __shfl_up_sync(FULL, la1, 1);
            const float hv = (w > 0) ? halo_s[pr][w - 1] : NEGF;
            if (lane == 0) P1 = hv;

            // Updates (all read OLD values):
            //  l1 = 2tid+1: from {l1, l0, l1-2 = left la1}  -> lse3
            //  l0 = 2tid  : from {l0, l0-1 = left la1}      -> lse2 (blank: no skip)
            const float t1 = lse3_2(la1, la0, sk1 ? P1 : NEGF) + er.y;
            const float t0 = lse2_2(la0, P1) + er.x;
            la1 = t1; la0 = t0;

            if (lane == 31) halo_s[pw][w] = la1;
            __syncthreads();

            er = nx;
        }

        // Refill the just-consumed chunk (slot k&3) with rows tb+32..tb+39.
        {
            const float*  src  = base + (size_t)(tb + 32) * strideT;
            const uint32_t dst0 = smem0 + (uint32_t)pos * (TPB * 8u);
#pragma unroll
            for (int j = 0; j < CH; ++j)
                cp8(dst0 + (uint32_t)j * (TPB * 8u), src + (size_t)j * strideT);
            cp_commit();
        }
    }
    cp_wait<0>();

    // ---- Tail: remaining < 8 steps, direct global loads ---------------------
    for (int t = tb; t < il; ++t) {
        const float* p = base + (size_t)t * strideT;
        const float e0 = p[0], e1 = p[1];

        const int pr = (t - 1) & 1;
        const int pw = t & 1;

        float P1 = __shfl_up_sync(FULL, la1, 1);
        const float hv = (w > 0) ? halo_s[pr][w - 1] : NEGF;
        if (lane == 0) P1 = hv;

        const float t1 = lse3_2(la1, la0, sk1 ? P1 : NEGF) + e1;
        const float t0 = lse2_2(la0, P1) + e0;
        la1 = t1; la0 = t0;

        if (lane == 31) halo_s[pw][w] = la1;
        __syncthreads();
    }

    // ---- Final cells: columns 2*tl (even -> thread tl, la0) and 2*tl-1
    //      (odd -> thread tl-1, la1), log2 units. ------------------------------
    if (tid == tl) fin[0] = la0;
    if (tl >= 1 && tid == tl - 1) fin[1] = la1;
    __syncthreads();

    if (tid == 0) {
        const float x1 = fin[0];
        const float x2 = fin[1];
        const float m  = fmaxf(x1, x2);
        float loss = -LN2 * (m + lg2f(ex2f(x1 - m) + ex2f(x2 - m)));
        if (!(loss < 5.0e29f)) loss = 0.0f;        // zero_infinity
        g_loss[b] = loss;
        __threadfence();
        const unsigned n = atomicAdd(&g_done, 1u);
        if (n == (unsigned)(gridDim.x - 1)) s_last = 1;
    }
    __syncthreads();

    // Last-arriving CTA: warp 0 reduces g_loss -> out[0].
    if (s_last && w == 0) {
        float s = 0.0f;
        for (int i = lane; i < B; i += 32) s += g_loss[i];
#pragma unroll
        for (int o = 16; o; o >>= 1) s += __shfl_xor_sync(FULL, s, o);
        if (lane == 0) {
            out[0] = s;
            g_done = 0u;
        }
    }
}

extern "C" void kernel_launch(void* const* d_in, const int* in_sizes, int n_in,
                              void* d_out, int out_size)
{
    const float* logp        = (const float*)d_in[0];
    const int*   targets     = (const int*)  d_in[1];
    const int*   input_lens  = (const int*)  d_in[2];
    const int*   target_lens = (const int*)  d_in[3];

    const int B = in_sizes[2];
    const int S = in_sizes[1] / B;
    const int C = 1000;
    const int T = (int)((long long)in_sizes[0] / ((long long)B * (long long)C));

    const int L = 2 * S + 1;              // requires L <= 256 (S <= 127)

    ctc_emit_kernel<<<T * B, 256>>>(logp, targets, target_lens, B, C, S, L);
    ctc_alpha_kernel<<<B, TPB>>>(targets, input_lens, target_lens,
                                 (float*)d_out, B, S);
}

// round 14
// speedup vs baseline: 2.7799x; 1.0334x over previous
#include <cuda_runtime.h>
#include <cstdint>

// ---------------------------------------------------------------------------
// CTC loss (forward, sum over batch, zero_infinity) on GB300 — SINGLE fused
// kernel. One CTA of 128 threads (4 warps) per batch element.
//
// Thread tid owns trellis columns 2*tid (blank: lse2, never skips) and
// 2*tid+1 (label: lse3). Log2-domain lse with exact median-of-3 (ex2 args
// <= 0: overflow/NaN free). Cross-warp halo via parity-double-buffered smem
// + one __syncthreads per step; intra-warp halo via shfl_up.
//
// The emit gather is FUSED: each thread cp.async's its label logp value
// (4 bytes, scattered) directly into its OWN ring slot (own wait_group ->
// own LDS read: no cross-thread visibility needed). The blank column's value
// (identical for all threads) goes into a 32-entry broadcast ring filled by
// thread 0 and staged after the per-step barrier. Chunked commit groups:
// 1 commit + 1 wait_group<2> per 8 steps (~24 rows of latency cover).
// No emit kernel, no g_em scratch: DRAM traffic ~halved.
// ---------------------------------------------------------------------------

#define NEGF (-1.0e30f)
#define LOG2E 1.4426950408889634f
#define LN2   0.6931471805599453f
#define TPB   128
#define NW    4
#define CH    8                          // rows per chunk
#define NCH   4                          // chunks in ring
#define RROWS 32

__device__ float g_loss[8192];
__device__ unsigned g_done;

__device__ __forceinline__ float ex2f(float x) {
    float r; asm("ex2.approx.f32 %0, %1;" : "=f"(r) : "f"(x)); return r;
}
__device__ __forceinline__ float lg2f(float x) {
    float r; asm("lg2.approx.f32 %0, %1;" : "=f"(r) : "f"(x)); return r;
}
__device__ __forceinline__ void cp4(uint32_t dst, const float* src) {
    asm volatile("cp.async.ca.shared.global [%0], [%1], 4;"
                 :: "r"(dst), "l"(src) : "memory");
}
__device__ __forceinline__ void cp_commit() {
    asm volatile("cp.async.commit_group;" ::: "memory");
}
template <int N>
__device__ __forceinline__ void cp_wait() {
    asm volatile("cp.async.wait_group %0;" :: "n"(N) : "memory");
}

// log2-domain lse3, exact median-of-3 (both ex2 args <= 0).
__device__ __forceinline__ float lse3_2(float a0, float a1, float a2) {
    const float mx01 = fmaxf(a0, a1);
    const float mn01 = fminf(a0, a1);
    const float mx   = fmaxf(mx01, a2);
    const float md   = fmaxf(mn01, fminf(mx01, a2));
    const float mn   = fminf(mn01, a2);
    return mx + lg2f(1.0f + ex2f(md - mx) + ex2f(mn - mx));
}
// log2-domain lse2.
__device__ __forceinline__ float lse2_2(float a0, float a1) {
    const float mx = fmaxf(a0, a1);
    const float mn = fminf(a0, a1);
    return mx + lg2f(1.0f + ex2f(mn - mx));
}

__global__ void __launch_bounds__(TPB, 1)
ctc_fused_kernel(const float* __restrict__ logp,
                 const int*   __restrict__ targets,
                 const int*   __restrict__ input_lens,
                 const int*   __restrict__ target_lens,
                 float* __restrict__ out,
                 int B, int C, int S)
{
    __shared__ __align__(16) float ring_l[RROWS][TPB];   // label logp, 16 KB
    __shared__ __align__(16) float ring_b[RROWS];        // blank logp (broadcast)
    __shared__ float halo_s[2][NW];
    __shared__ float fin[2];
    __shared__ int   s_last;

    const int b    = blockIdx.x;
    const int tid  = threadIdx.x;
    const int lane = tid & 31;
    const int w    = tid >> 5;
    const unsigned FULL = 0xffffffffu;

    const int tl = target_lens[b];
    const int il = input_lens[b];
    const int Lb = 2 * tl + 1;

    // Label + skip flag for the odd column l1 = 2*tid+1 (even col never skips).
    int  e1  = 0;
    bool sk1 = false;
    if (tid < S) {
        e1 = targets[b * S + tid];
        const int l1 = 2 * tid + 1;
        if (l1 >= 3 && l1 < Lb) sk1 = (e1 != targets[b * S + tid - 1]);
    }

    const size_t strideT = (size_t)B * C;                   // floats per timestep
    const float* pb = logp + (size_t)b * C;                 // blank (class 0)
    const float* pl = logp + (size_t)b * C + e1;            // this thread's label

    const uint32_t rl0 = (uint32_t)__cvta_generic_to_shared(&ring_l[0][0]);
    const uint32_t rb0 = (uint32_t)__cvta_generic_to_shared(&ring_b[0]);

    // t = 0 init: columns 0,1 (thread 0) from logp row 0; all else -1e30.
    float la0 = NEGF, la1 = NEGF;
    if (tid == 0) {
        la0 = pb[0] * LOG2E;
        la1 = pl[0] * LOG2E;
    }
    if (lane == 31) halo_s[0][w] = la1;     // parity 0, read at t = 1
    if (tid == 0) { fin[1] = NEGF; s_last = 0; }

    // ---- Prologue: rows 1..32 into the rings, one commit group per chunk ----
#pragma unroll
    for (int c = 0; c < NCH; ++c) {
#pragma unroll
        for (int j = 0; j < CH; ++j) {
            const int rr  = c * CH + j;                 // ring row = global row-1
            const int row = min(1 + rr, il - 1);
            cp4(rl0 + (uint32_t)rr * (TPB * 4u) + (uint32_t)tid * 4u,
                pl + (size_t)row * strideT);
            if (tid == 0)
                cp4(rb0 + (uint32_t)rr * 4u, pb + (size_t)row * strideT);
        }
        cp_commit();
    }
    cp_wait<2>();                          // own copies: chunks 0,1 resident
    __syncthreads();                       // publishes ring_b row 1 + halo_s[0]
    float erl = ring_l[0][tid];            // row 1 staged
    float erb = ring_b[0];

    // ---- Main loop: 1 wait + 1 commit per 8 steps; 1 bar per step -----------
    int tb = 1;
    int k  = 0;
    for (; tb + CH <= il; tb += CH, ++k) {
        cp_wait<2>();                      // own copies for rows <= tb+23 done
        const int pos = (8 * k) & 31;      // ring row of global row tb

#pragma unroll
        for (int j = 0; j < CH; ++j) {
            // parities: tb odd -> (t-1)&1 == j&1.
            const int pr = j & 1;
            const int pw = (j + 1) & 1;

            // Halo: old la1 of the column to the left (l = 2*tid - 1).
            float P1 = __shfl_up_sync(FULL, la1, 1);
            const float hv = (w > 0) ? halo_s[pr][w - 1] : NEGF;
            if (lane == 0) P1 = hv;

            // Updates (read OLD values); emit added via fma (raw logp * LOG2E).
            const float t1 = lse3_2(la1, la0, sk1 ? P1 : NEGF);
            const float t0 = lse2_2(la0, P1);
            la1 = fmaf(erl, LOG2E, t1);
            la0 = fmaf(erb, LOG2E, t0);

            if (lane == 31) halo_s[pw][w] = la1;
            __syncthreads();

            // Stage row t+1 (post-bar: ring_b written by thread 0's cp.async,
            // published by its chunk-start wait + this barrier).
            const int rr = (pos + 1 + j) & 31;
            erl = ring_l[rr][tid];
            erb = ring_b[rr];
        }

        // Refill the consumed chunk (ring rows pos..pos+7) with rows tb+32..39.
#pragma unroll
        for (int j = 0; j < CH; ++j) {
            const int row = min(tb + 32 + j, il - 1);
            const int rr  = pos + j;
            cp4(rl0 + (uint32_t)rr * (TPB * 4u) + (uint32_t)tid * 4u,
                pl + (size_t)row * strideT);
            if (tid == 0)
                cp4(rb0 + (uint32_t)rr * 4u, pb + (size_t)row * strideT);
        }
        cp_commit();
    }
    cp_wait<0>();                          // drain before tail / exit

    // ---- Tail: remaining < 8 steps, direct global loads ---------------------
    for (int t = tb; t < il; ++t) {
        const float el = __ldg(pl + (size_t)t * strideT);
        const float eb = __ldg(pb + (size_t)t * strideT);

        const int pr = (t - 1) & 1;
        const int pw = t & 1;

        float P1 = __shfl_up_sync(FULL, la1, 1);
        const float hv = (w > 0) ? halo_s[pr][w - 1] : NEGF;
        if (lane == 0) P1 = hv;

        const float t1 = lse3_2(la1, la0, sk1 ? P1 : NEGF);
        const float t0 = lse2_2(la0, P1);
        la1 = fmaf(el, LOG2E, t1);
        la0 = fmaf(eb, LOG2E, t0);

        if (lane == 31) halo_s[pw][w] = la1;
        __syncthreads();
    }

    // ---- Final cells: col 2*tl (thread tl, la0), col 2*tl-1 (thread tl-1, la1)
    if (tid == tl) fin[0] = la0;
    if (tl >= 1 && tid == tl - 1) fin[1] = la1;
    __syncthreads();

    if (tid == 0) {
        const float x1 = fin[0];
        const float x2 = fin[1];
        const float m  = fmaxf(x1, x2);
        float loss = -LN2 * (m + lg2f(ex2f(x1 - m) + ex2f(x2 - m)));
        if (!(loss < 5.0e29f)) loss = 0.0f;        // zero_infinity
        g_loss[b] = loss;
        __threadfence();
        const unsigned n = atomicAdd(&g_done, 1u);
        if (n == (unsigned)(gridDim.x - 1)) s_last = 1;
    }
    __syncthreads();

    // Last-arriving CTA: warp 0 reduces g_loss -> out[0].
    if (s_last && w == 0) {
        float s = 0.0f;
        for (int i = lane; i < B; i += 32) s += g_loss[i];
#pragma unroll
        for (int o = 16; o; o >>= 1) s += __shfl_xor_sync(FULL, s, o);
        if (lane == 0) {
            out[0] = s;
            g_done = 0u;
        }
    }
}

extern "C" void kernel_launch(void* const* d_in, const int* in_sizes, int n_in,
                              void* d_out, int out_size)
{
    const float* logp        = (const float*)d_in[0];
    const int*   targets     = (const int*)  d_in[1];
    const int*   input_lens  = (const int*)  d_in[2];
    const int*   target_lens = (const int*)  d_in[3];

    const int B = in_sizes[2];
    const int S = in_sizes[1] / B;
    const int C = 1000;                   // class count (dataset constant)

    ctc_fused_kernel<<<B, TPB>>>(logp, targets, input_lens, target_lens,
                                 (float*)d_out, B, C, S);
}